// round 3
// baseline (speedup 1.0000x reference)
#include <cuda_runtime.h>
#include <cuda_bf16.h>

// CRF NLL, B x T x K=9 (START=7, STOP=8), 7 live states.
// Linear-domain parallel time-chunk scan with periodic rescaling.
// 8-lane groups: lanes 0..6 evolve one operator column each, lane 7 does gold.
// Matrix path uses packed f32x2 FMA (row-pairs) to halve fma-pipe pressure.

#define NCH 32
#define NS  7
#define KK  9
#define MAXB 2048

typedef unsigned long long ull;

__device__ float g_scratch[(size_t)NCH * MAXB * 64]; // [(c*B+b)*64 + s*8 + j]
__device__ float g_gold[NCH * MAXB];
__device__ int   g_perm[MAXB];
__device__ float g_accum = 0.f;
__device__ int   g_done  = 0;

__device__ __forceinline__ ull pk2(float x, float y) {
    ull d; asm("mov.b64 %0, {%1,%2};" : "=l"(d) : "f"(x), "f"(y)); return d;
}
__device__ __forceinline__ void upk2(ull d, float& x, float& y) {
    asm("mov.b64 {%0,%1}, %2;" : "=f"(x), "=f"(y) : "l"(d));
}
__device__ __forceinline__ ull ffma2(ull a, ull b, ull c) {
    ull d; asm("fma.rn.f32x2 %0, %1, %2, %3;" : "=l"(d) : "l"(a), "l"(b), "l"(c));
    return d;
}
__device__ __forceinline__ ull fmul2(ull a, ull b) {
    ull d; asm("mul.rn.f32x2 %0, %1, %2;" : "=l"(d) : "l"(a), "l"(b)); return d;
}

__device__ __forceinline__ int bucket_of(int L, int C0, int Cm) {
    int bk = (L <= C0) ? 0 : 1 + (L - C0 - 1) / Cm;
    return bk > NCH - 1 ? NCH - 1 : bk;
}

// ---------------------------------------------------------------------------
__global__ void perm_kernel(const int* __restrict__ lengths, int B, int C0, int Cm)
{
    __shared__ int hist[NCH];
    __shared__ int off[NCH];
    int tid = threadIdx.x;
    if (tid < NCH) hist[tid] = 0;
    __syncthreads();
    for (int b = tid; b < B; b += blockDim.x)
        atomicAdd(&hist[bucket_of(lengths[b], C0, Cm)], 1);
    __syncthreads();
    if (tid == 0) {
        int acc = 0;
        for (int i = 0; i < NCH; i++) { off[i] = acc; acc += hist[i]; }
    }
    __syncthreads();
    for (int b = tid; b < B; b += blockDim.x) {
        int pos = atomicAdd(&off[bucket_of(lengths[b], C0, Cm)], 1);
        g_perm[pos] = b;
    }
}

// ---------------------------------------------------------------------------
__global__ void __launch_bounds__(256) chunk_kernel(
    const float* __restrict__ feats, const float* __restrict__ trans,
    const int* __restrict__ tags, const int* __restrict__ lengths,
    int B, int T, int C0, int Cm)
{
    __shared__ float s_tr[KK * KK];
    __shared__ float s_et[NS * NS];
    int tid = threadIdx.x;
    if (tid < KK * KK) s_tr[tid] = trans[tid];
    __syncthreads();
    if (tid < NS * NS) s_et[tid] = __expf(s_tr[(tid / NS) * KK + (tid % NS)]);
    __syncthreads();

    int g = (blockIdx.x * blockDim.x + tid) >> 3;
    if (g >= NCH * B) return;
    int lane = tid & 7;
    unsigned grpw  = (unsigned)(tid & 31) & 24u;
    unsigned mask8 = 0xFFu << grpw;

    int c = g / B;
    int slot = g - c * B;
    int b = g_perm[slot];
    int L = lengths[b];
    int t0 = (c == 0) ? 0 : C0 + (c - 1) * Cm;
    if (t0 >= L) return;               // whole group exits together
    int t1 = min(L, (c == 0) ? C0 : t0 + Cm);

    const float* fb  = feats + (size_t)b * T * KK;
    const int*   tgb = tags  + (size_t)b * T;
    size_t base = ((size_t)c * B + b) * 64;

    float gold = 0.f;
    int prev = 0;

    if (c == 0) {
        // -------- vector path: lane j holds alpha[j] --------
        float etrow[NS];
        int jr = (lane < NS) ? lane : 0;
        #pragma unroll
        for (int i = 0; i < NS; i++) etrow[i] = s_et[jr * NS + i];

        // t = 0: alpha[j] = trans[j,START] + feat[0,j]
        float fv = 0.f;
        if (lane < NS) fv = __ldg(&fb[lane]);
        float x = (lane < NS) ? (s_tr[lane * KK + 7] + fv) : -1e30f;
        float m = x;
        #pragma unroll
        for (int d = 1; d < 8; d <<= 1) m = fmaxf(m, __shfl_xor_sync(mask8, m, d));
        float a = (lane < NS) ? __expf(x - m) : 0.f;
        float csc = m;
        if (lane == 7) {
            int tg = __ldg(&tgb[0]);
            gold = s_tr[tg * KK + 7] + __ldg(&fb[tg]);
            prev = tg;
        }

        int rc = 0;
        for (int t = 1; t < t1; ++t) {
            float f2 = 0.f;
            if (lane < NS) f2 = __ldg(&fb[t * KK + lane]);
            else {
                int tg2 = __ldg(&tgb[t]);
                gold += s_tr[tg2 * KK + prev] + __ldg(&fb[t * KK + tg2]);
                prev = tg2;
            }
            float efl = __expf(f2);
            float a0 = __shfl_sync(mask8, a, grpw + 0);
            float a1 = __shfl_sync(mask8, a, grpw + 1);
            float a2 = __shfl_sync(mask8, a, grpw + 2);
            float a3 = __shfl_sync(mask8, a, grpw + 3);
            float a4 = __shfl_sync(mask8, a, grpw + 4);
            float a5 = __shfl_sync(mask8, a, grpw + 5);
            float a6 = __shfl_sync(mask8, a, grpw + 6);
            float nv = etrow[0] * a0;
            nv = fmaf(etrow[1], a1, nv);
            nv = fmaf(etrow[2], a2, nv);
            nv = fmaf(etrow[3], a3, nv);
            nv = fmaf(etrow[4], a4, nv);
            nv = fmaf(etrow[5], a5, nv);
            nv = fmaf(etrow[6], a6, nv);
            if (lane < NS) a = nv * efl;
            if (++rc == 4) {
                rc = 0;
                float mm = a;
                #pragma unroll
                for (int d = 1; d < 8; d <<= 1)
                    mm = fmaxf(mm, __shfl_xor_sync(mask8, mm, d));
                mm = fmaxf(mm, 1e-30f);
                float inv = __fdividef(1.f, mm);
                if (lane < NS) a *= inv;
                csc += __logf(mm);
            }
        }
        float mm = a;
        #pragma unroll
        for (int d = 1; d < 8; d <<= 1)
            mm = fmaxf(mm, __shfl_xor_sync(mask8, mm, d));
        mm = fmaxf(mm, 1e-30f);
        float inv = __fdividef(1.f, mm);
        if (lane < NS) a *= inv;
        csc += __logf(mm);

        if (lane < NS) g_scratch[base + lane] = a;
        if (lane == 7) {
            g_scratch[base + 7] = csc;
            g_gold[b] = gold;          // c == 0
        }
    } else {
        // -------- matrix path (f32x2): lane s evolves operator column s ----
        // Row pairs (0,1),(2,3),(4,5),(6,6): etp[p][i] = (et[2p][i], et[j1][i])
        ull etp[4][NS];
        #pragma unroll
        for (int p = 0; p < 4; p++) {
            int j0 = 2 * p, j1 = (2 * p + 1 < NS) ? 2 * p + 1 : NS - 1;
            #pragma unroll
            for (int i = 0; i < NS; i++)
                etp[p][i] = pk2(s_et[j0 * NS + i], s_et[j1 * NS + i]);
        }

        float v[NS];
        #pragma unroll
        for (int j = 0; j < NS; j++) v[j] = (j == lane) ? 1.f : 0.f; // lane7: 0s
        float csc = 0.f;
        if (lane == 7) prev = __ldg(&tgb[t0 - 1]);

        int rc = 0;
        for (int t = t0; t < t1; ++t) {
            float fv = 0.f;
            if (lane < NS) fv = __ldg(&fb[t * KK + lane]);
            else {
                int tg = __ldg(&tgb[t]);
                gold += s_tr[tg * KK + prev] + __ldg(&fb[t * KK + tg]);
                prev = tg;
            }
            float efl = __expf(fv);
            float e0 = __shfl_sync(mask8, efl, grpw + 0);
            float e1 = __shfl_sync(mask8, efl, grpw + 1);
            float e2 = __shfl_sync(mask8, efl, grpw + 2);
            float e3 = __shfl_sync(mask8, efl, grpw + 3);
            float e4 = __shfl_sync(mask8, efl, grpw + 4);
            float e5 = __shfl_sync(mask8, efl, grpw + 5);
            float e6 = __shfl_sync(mask8, efl, grpw + 6);

            ull dv0 = pk2(v[0], v[0]);
            ull dv1 = pk2(v[1], v[1]);
            ull dv2 = pk2(v[2], v[2]);
            ull dv3 = pk2(v[3], v[3]);
            ull dv4 = pk2(v[4], v[4]);
            ull dv5 = pk2(v[5], v[5]);
            ull dv6 = pk2(v[6], v[6]);

            ull a0 = fmul2(etp[0][0], dv0);
            ull a1 = fmul2(etp[1][0], dv0);
            ull a2 = fmul2(etp[2][0], dv0);
            ull a3 = fmul2(etp[3][0], dv0);
            a0 = ffma2(etp[0][1], dv1, a0); a1 = ffma2(etp[1][1], dv1, a1);
            a2 = ffma2(etp[2][1], dv1, a2); a3 = ffma2(etp[3][1], dv1, a3);
            a0 = ffma2(etp[0][2], dv2, a0); a1 = ffma2(etp[1][2], dv2, a1);
            a2 = ffma2(etp[2][2], dv2, a2); a3 = ffma2(etp[3][2], dv2, a3);
            a0 = ffma2(etp[0][3], dv3, a0); a1 = ffma2(etp[1][3], dv3, a1);
            a2 = ffma2(etp[2][3], dv3, a2); a3 = ffma2(etp[3][3], dv3, a3);
            a0 = ffma2(etp[0][4], dv4, a0); a1 = ffma2(etp[1][4], dv4, a1);
            a2 = ffma2(etp[2][4], dv4, a2); a3 = ffma2(etp[3][4], dv4, a3);
            a0 = ffma2(etp[0][5], dv5, a0); a1 = ffma2(etp[1][5], dv5, a1);
            a2 = ffma2(etp[2][5], dv5, a2); a3 = ffma2(etp[3][5], dv5, a3);
            a0 = ffma2(etp[0][6], dv6, a0); a1 = ffma2(etp[1][6], dv6, a1);
            a2 = ffma2(etp[2][6], dv6, a2); a3 = ffma2(etp[3][6], dv6, a3);

            float n0, n1, n2, n3, n4, n5, n6, n7;
            upk2(a0, n0, n1); upk2(a1, n2, n3);
            upk2(a2, n4, n5); upk2(a3, n6, n7);
            v[0] = n0 * e0; v[1] = n1 * e1; v[2] = n2 * e2; v[3] = n3 * e3;
            v[4] = n4 * e4; v[5] = n5 * e5; v[6] = n6 * e6;

            if (++rc == 4) {
                rc = 0;
                float mm = v[0];
                #pragma unroll
                for (int j = 1; j < NS; j++) mm = fmaxf(mm, v[j]);
                mm = fmaxf(mm, 1e-30f);
                float inv = __fdividef(1.f, mm);
                #pragma unroll
                for (int j = 0; j < NS; j++) v[j] *= inv;
                csc += __logf(mm);
            }
        }
        float mm = v[0];
        #pragma unroll
        for (int j = 1; j < NS; j++) mm = fmaxf(mm, v[j]);
        mm = fmaxf(mm, 1e-30f);
        float inv = __fdividef(1.f, mm);
        #pragma unroll
        for (int j = 0; j < NS; j++) v[j] *= inv;
        csc += __logf(mm);

        if (lane < NS) {
            #pragma unroll
            for (int j = 0; j < NS; j++)
                g_scratch[base + lane * 8 + j] = v[j];
            g_scratch[base + lane * 8 + 7] = csc;
        } else {
            g_gold[c * B + b] = gold;
        }
    }
}

// ---------------------------------------------------------------------------
// Fold chunk operators per sentence, finish scores, atomically accumulate
// mean; last block writes the output and resets the accumulators.
// ---------------------------------------------------------------------------
__global__ void __launch_bounds__(256) combine_kernel(
    const float* __restrict__ trans, const int* __restrict__ tags,
    const int* __restrict__ lengths, float* __restrict__ out,
    int B, int T, int C0, int Cm)
{
    int tid = threadIdx.x;
    int g = (blockIdx.x * blockDim.x + tid) >> 3;
    int lane = tid & 7;
    unsigned grpw  = (unsigned)(tid & 31) & 24u;
    unsigned mask8 = 0xFFu << grpw;

    if (g < B) {
        int b = g_perm[g];
        int L = lengths[b];

        float v  = (lane < NS) ? g_scratch[(size_t)b * 64 + lane] : 0.f;
        float sc = g_scratch[(size_t)b * 64 + 7];
        float gold = (lane == 7) ? g_gold[b] : 0.f;

        for (int c = 1; c < NCH; ++c) {
            int t0c = C0 + (c - 1) * Cm;
            if (t0c >= L) break;
            size_t base = ((size_t)c * B + b) * 64;
            float cs = (lane < NS) ? g_scratch[base + lane * 8 + 7] : -1e30f;
            float csmax = cs;
            #pragma unroll
            for (int d = 1; d < 8; d <<= 1)
                csmax = fmaxf(csmax, __shfl_xor_sync(mask8, csmax, d));
            float w = (lane < NS) ? v * __expf(cs - csmax) : 0.f;
            float nv = 0.f;
            #pragma unroll
            for (int s = 0; s < NS; ++s) {
                float ws = __shfl_sync(mask8, w, grpw + (unsigned)s);
                float M = g_scratch[base + s * 8 + lane];
                nv = fmaf(M, ws, nv);
            }
            if (lane == 7) nv = 0.f;
            float mm = nv;
            #pragma unroll
            for (int d = 1; d < 8; d <<= 1)
                mm = fmaxf(mm, __shfl_xor_sync(mask8, mm, d));
            mm = fmaxf(mm, 1e-30f);
            v = nv * __fdividef(1.f, mm);
            sc += csmax + __logf(mm);
            if (lane == 7) gold += g_gold[c * B + b];
        }

        float term = (lane < NS) ? v * __expf(__ldg(&trans[8 * KK + lane])) : 0.f;
        #pragma unroll
        for (int d = 1; d < 8; d <<= 1)
            term += __shfl_xor_sync(mask8, term, d);
        float fwd = sc + __logf(term);
        if (lane == 7) {
            int last = __ldg(&tags[(size_t)b * T + (L - 1)]);
            gold += __ldg(&trans[8 * KK + last]);
            float r = atomicAdd(&g_accum, fwd - gold);
            (void)r;
            __threadfence();
        }
    }

    __syncthreads();
    if (tid == 0) {
        __threadfence();
        int old = atomicAdd(&g_done, 1);
        if (old == (int)gridDim.x - 1) {
            __threadfence();
            float tot = *((volatile float*)&g_accum);
            out[0] = tot / (float)B;
            *((volatile float*)&g_accum) = 0.f;
            __threadfence();
            *((volatile int*)&g_done) = 0;
        }
    }
}

extern "C" void kernel_launch(void* const* d_in, const int* in_sizes, int n_in,
                              void* d_out, int out_size)
{
    const float* feats   = (const float*)d_in[0];
    const float* trans   = (const float*)d_in[1];
    const int*   tags    = (const int*)d_in[2];
    const int*   lengths = (const int*)d_in[3];

    int B = in_sizes[3];
    int T = in_sizes[2] / B;

    // Uneven chunks: chunk 0 (cheap vector recurrence) gets ~T/8 steps,
    // remaining NCH-1 chunks (expensive matrix recurrence) split the rest.
    int C0 = T / 8; if (C0 < 1) C0 = 1;
    int Cm = (T - C0 + NCH - 2) / (NCH - 1); if (Cm < 1) Cm = 1;

    perm_kernel<<<1, 1024>>>(lengths, B, C0, Cm);
    int thr = NCH * B * 8;
    chunk_kernel<<<(thr + 255) / 256, 256>>>(feats, trans, tags, lengths, B, T, C0, Cm);
    combine_kernel<<<(B * 8 + 255) / 256, 256>>>(trans, tags, lengths,
                                                 (float*)d_out, B, T, C0, Cm);
}

// round 4
// speedup vs baseline: 1.2841x; 1.2841x over previous
#include <cuda_runtime.h>
#include <cuda_bf16.h>

// CRF NLL, B x T x K=9 (START=7, STOP=8), 7 live states.
// gold_kernel: embarrassingly-parallel gold path score (warp per sentence).
// chunk_kernel: linear-domain parallel time-chunk scan, 8-lane groups,
//               lanes 0..6 evolve one operator column each (pure scan, no gold).
// combine_kernel: fold chunk operators per sentence + fused mean reduction.

#define NCH 32
#define NS  7
#define KK  9
#define MAXB 2048

__device__ float g_scratch[(size_t)NCH * MAXB * 64]; // [(c*B+b)*64 + s*8 + j]
__device__ float g_gold[MAXB];
__device__ int   g_perm[MAXB];
__device__ float g_accum = 0.f;
__device__ int   g_done  = 0;

// ---------------------------------------------------------------------------
__global__ void perm_kernel(const int* __restrict__ lengths, int B, int C)
{
    __shared__ int hist[NCH];
    __shared__ int off[NCH];
    int tid = threadIdx.x;
    if (tid < NCH) hist[tid] = 0;
    __syncthreads();
    for (int b = tid; b < B; b += blockDim.x) {
        int bk = (lengths[b] - 1) / C;
        if (bk > NCH - 1) bk = NCH - 1;
        atomicAdd(&hist[bk], 1);
    }
    __syncthreads();
    if (tid == 0) {
        int acc = 0;
        for (int i = 0; i < NCH; i++) { off[i] = acc; acc += hist[i]; }
    }
    __syncthreads();
    for (int b = tid; b < B; b += blockDim.x) {
        int bk = (lengths[b] - 1) / C;
        if (bk > NCH - 1) bk = NCH - 1;
        int pos = atomicAdd(&off[bk], 1);
        g_perm[pos] = b;
    }
}

// ---------------------------------------------------------------------------
// Gold path score: no recurrence -> warp-parallel over time.
// ---------------------------------------------------------------------------
__global__ void __launch_bounds__(256) gold_kernel(
    const float* __restrict__ feats, const float* __restrict__ trans,
    const int* __restrict__ tags, const int* __restrict__ lengths,
    int B, int T)
{
    int w = (blockIdx.x * blockDim.x + threadIdx.x) >> 5;
    if (w >= B) return;
    int lane = threadIdx.x & 31;
    int L = lengths[w];
    const int*   tgb = tags  + (size_t)w * T;
    const float* fb  = feats + (size_t)w * T * KK;

    float acc = 0.f;
    for (int t = lane; t < L; t += 32) {
        int tg = __ldg(&tgb[t]);
        int pv = (t == 0) ? 7 : __ldg(&tgb[t - 1]);
        acc += __ldg(&trans[tg * KK + pv]) + __ldg(&fb[t * KK + tg]);
    }
    #pragma unroll
    for (int d = 16; d; d >>= 1) acc += __shfl_xor_sync(0xFFFFFFFFu, acc, d);
    if (lane == 0) {
        int last = __ldg(&tgb[L - 1]);
        g_gold[w] = acc + __ldg(&trans[8 * KK + last]);
    }
}

// ---------------------------------------------------------------------------
__global__ void __launch_bounds__(256) chunk_kernel(
    const float* __restrict__ feats, const float* __restrict__ trans,
    const int* __restrict__ lengths, int B, int T, int C)
{
    __shared__ float s_tr[KK * KK];
    __shared__ float s_et[NS * NS];
    int tid = threadIdx.x;
    if (tid < KK * KK) s_tr[tid] = trans[tid];
    __syncthreads();
    if (tid < NS * NS) s_et[tid] = __expf(s_tr[(tid / NS) * KK + (tid % NS)]);
    __syncthreads();

    int g = (blockIdx.x * blockDim.x + tid) >> 3;
    if (g >= NCH * B) return;
    int lane = tid & 7;
    unsigned grpw  = (unsigned)(tid & 31) & 24u;
    unsigned mask8 = 0xFFu << grpw;

    int c = g / B;
    int slot = g - c * B;
    int b = g_perm[slot];
    int L = lengths[b];
    int t0 = c * C;
    if (t0 >= L) return;               // whole 8-lane group exits together
    int t1 = min(L, t0 + C);

    const float* fb = feats + (size_t)b * T * KK;
    size_t base = ((size_t)c * B + b) * 64;

    if (c == 0) {
        // -------- vector path: lane j holds alpha[j] --------
        float etrow[NS];
        int jr = (lane < NS) ? lane : 0;
        #pragma unroll
        for (int i = 0; i < NS; i++) etrow[i] = s_et[jr * NS + i];

        // t = 0: alpha[j] = trans[j,START] + feat[0,j]
        float fv = 0.f;
        if (lane < NS) fv = __ldg(&fb[lane]);
        float x = (lane < NS) ? (s_tr[lane * KK + 7] + fv) : -1e30f;
        float m = x;
        #pragma unroll
        for (int d = 1; d < 8; d <<= 1) m = fmaxf(m, __shfl_xor_sync(mask8, m, d));
        float a = (lane < NS) ? __expf(x - m) : 0.f;
        float csc = m;

        int rc = 0;
        for (int t = 1; t < t1; ++t) {
            float f2 = 0.f;
            if (lane < NS) f2 = __ldg(&fb[t * KK + lane]);
            float efl = __expf(f2);
            float a0 = __shfl_sync(mask8, a, grpw + 0);
            float a1 = __shfl_sync(mask8, a, grpw + 1);
            float a2 = __shfl_sync(mask8, a, grpw + 2);
            float a3 = __shfl_sync(mask8, a, grpw + 3);
            float a4 = __shfl_sync(mask8, a, grpw + 4);
            float a5 = __shfl_sync(mask8, a, grpw + 5);
            float a6 = __shfl_sync(mask8, a, grpw + 6);
            float nv = etrow[0] * a0;
            nv = fmaf(etrow[1], a1, nv);
            nv = fmaf(etrow[2], a2, nv);
            nv = fmaf(etrow[3], a3, nv);
            nv = fmaf(etrow[4], a4, nv);
            nv = fmaf(etrow[5], a5, nv);
            nv = fmaf(etrow[6], a6, nv);
            if (lane < NS) a = nv * efl;
            if (++rc == 4) {
                rc = 0;
                float mm = a;
                #pragma unroll
                for (int d = 1; d < 8; d <<= 1)
                    mm = fmaxf(mm, __shfl_xor_sync(mask8, mm, d));
                mm = fmaxf(mm, 1e-30f);
                float inv = __fdividef(1.f, mm);
                if (lane < NS) a *= inv;
                csc += __logf(mm);
            }
        }
        float mm = a;
        #pragma unroll
        for (int d = 1; d < 8; d <<= 1)
            mm = fmaxf(mm, __shfl_xor_sync(mask8, mm, d));
        mm = fmaxf(mm, 1e-30f);
        float inv = __fdividef(1.f, mm);
        if (lane < NS) a *= inv;
        csc += __logf(mm);

        if (lane < NS) g_scratch[base + lane] = a;
        if (lane == 7) g_scratch[base + 7] = csc;
    } else {
        // -------- matrix path: lane s evolves operator column s --------
        float et[NS][NS];
        #pragma unroll
        for (int j = 0; j < NS; j++)
            #pragma unroll
            for (int i = 0; i < NS; i++) et[j][i] = s_et[j * NS + i];

        float v[NS];
        #pragma unroll
        for (int j = 0; j < NS; j++) v[j] = (j == lane) ? 1.f : 0.f; // lane7: 0s
        float csc = 0.f;

        int rc = 0;
        for (int t = t0; t < t1; ++t) {
            float fv = 0.f;
            if (lane < NS) fv = __ldg(&fb[t * KK + lane]);
            float efl = __expf(fv);
            float e0 = __shfl_sync(mask8, efl, grpw + 0);
            float e1 = __shfl_sync(mask8, efl, grpw + 1);
            float e2 = __shfl_sync(mask8, efl, grpw + 2);
            float e3 = __shfl_sync(mask8, efl, grpw + 3);
            float e4 = __shfl_sync(mask8, efl, grpw + 4);
            float e5 = __shfl_sync(mask8, efl, grpw + 5);
            float e6 = __shfl_sync(mask8, efl, grpw + 6);

            float nv[NS];
            #pragma unroll
            for (int j = 0; j < NS; j++) {
                float acc = et[j][0] * v[0];
                #pragma unroll
                for (int i = 1; i < NS; i++) acc = fmaf(et[j][i], v[i], acc);
                nv[j] = acc;
            }
            v[0] = nv[0] * e0; v[1] = nv[1] * e1; v[2] = nv[2] * e2;
            v[3] = nv[3] * e3; v[4] = nv[4] * e4; v[5] = nv[5] * e5;
            v[6] = nv[6] * e6;

            if (++rc == 4) {
                rc = 0;
                float mm = v[0];
                #pragma unroll
                for (int j = 1; j < NS; j++) mm = fmaxf(mm, v[j]);
                mm = fmaxf(mm, 1e-30f);
                float inv = __fdividef(1.f, mm);
                #pragma unroll
                for (int j = 0; j < NS; j++) v[j] *= inv;
                csc += __logf(mm);
            }
        }
        float mm = v[0];
        #pragma unroll
        for (int j = 1; j < NS; j++) mm = fmaxf(mm, v[j]);
        mm = fmaxf(mm, 1e-30f);
        float inv = __fdividef(1.f, mm);
        #pragma unroll
        for (int j = 0; j < NS; j++) v[j] *= inv;
        csc += __logf(mm);

        if (lane < NS) {
            #pragma unroll
            for (int j = 0; j < NS; j++)
                g_scratch[base + lane * 8 + j] = v[j];
            g_scratch[base + lane * 8 + 7] = csc;
        }
    }
}

// ---------------------------------------------------------------------------
// Fold chunk operators per sentence, finish forward score, subtract gold,
// atomically accumulate; last block writes mean and resets accumulators.
// ---------------------------------------------------------------------------
__global__ void __launch_bounds__(256) combine_kernel(
    const float* __restrict__ trans, const int* __restrict__ lengths,
    float* __restrict__ out, int B, int T, int C)
{
    int tid = threadIdx.x;
    int g = (blockIdx.x * blockDim.x + tid) >> 3;
    int lane = tid & 7;
    unsigned grpw  = (unsigned)(tid & 31) & 24u;
    unsigned mask8 = 0xFFu << grpw;

    if (g < B) {
        int b = g_perm[g];
        int L = lengths[b];

        float v  = (lane < NS) ? g_scratch[(size_t)b * 64 + lane] : 0.f;
        float sc = g_scratch[(size_t)b * 64 + 7];

        for (int c = 1; c < NCH && c * C < L; ++c) {
            size_t base = ((size_t)c * B + b) * 64;
            float cs = (lane < NS) ? g_scratch[base + lane * 8 + 7] : -1e30f;
            float csmax = cs;
            #pragma unroll
            for (int d = 1; d < 8; d <<= 1)
                csmax = fmaxf(csmax, __shfl_xor_sync(mask8, csmax, d));
            float w = (lane < NS) ? v * __expf(cs - csmax) : 0.f;
            float nv = 0.f;
            #pragma unroll
            for (int s = 0; s < NS; ++s) {
                float ws = __shfl_sync(mask8, w, grpw + (unsigned)s);
                float M = g_scratch[base + s * 8 + lane];
                nv = fmaf(M, ws, nv);
            }
            if (lane == 7) nv = 0.f;
            float mm = nv;
            #pragma unroll
            for (int d = 1; d < 8; d <<= 1)
                mm = fmaxf(mm, __shfl_xor_sync(mask8, mm, d));
            mm = fmaxf(mm, 1e-30f);
            v = nv * __fdividef(1.f, mm);
            sc += csmax + __logf(mm);
        }

        float term = (lane < NS) ? v * __expf(__ldg(&trans[8 * KK + lane])) : 0.f;
        #pragma unroll
        for (int d = 1; d < 8; d <<= 1)
            term += __shfl_xor_sync(mask8, term, d);
        float fwd = sc + __logf(term);
        if (lane == 7) {
            atomicAdd(&g_accum, fwd - g_gold[b]);
            __threadfence();
        }
    }

    __syncthreads();
    if (tid == 0) {
        __threadfence();
        int old = atomicAdd(&g_done, 1);
        if (old == (int)gridDim.x - 1) {
            __threadfence();
            float tot = *((volatile float*)&g_accum);
            out[0] = tot / (float)B;
            *((volatile float*)&g_accum) = 0.f;
            __threadfence();
            *((volatile int*)&g_done) = 0;
        }
    }
}

extern "C" void kernel_launch(void* const* d_in, const int* in_sizes, int n_in,
                              void* d_out, int out_size)
{
    const float* feats   = (const float*)d_in[0];
    const float* trans   = (const float*)d_in[1];
    const int*   tags    = (const int*)d_in[2];
    const int*   lengths = (const int*)d_in[3];

    int B = in_sizes[3];
    int T = in_sizes[2] / B;
    int C = (T + NCH - 1) / NCH;

    perm_kernel<<<1, 1024>>>(lengths, B, C);
    gold_kernel<<<(B * 32 + 255) / 256, 256>>>(feats, trans, tags, lengths, B, T);
    int thr = NCH * B * 8;
    chunk_kernel<<<(thr + 255) / 256, 256>>>(feats, trans, lengths, B, T, C);
    combine_kernel<<<(B * 8 + 255) / 256, 256>>>(trans, lengths,
                                                 (float*)d_out, B, T, C);
}